// round 2
// baseline (speedup 1.0000x reference)
#include <cuda_runtime.h>
#include <cuda_bf16.h>
#include <math.h>

#define NBATCH 2
#define NLR    4096
#define NPTS   (NBATCH*NLR)
#define SPLITS 8
#define MT     64

#define W3J_TOTAL   13318
#define W3J_OUT_OFF 2670
#define W3J_OUT_SZ  10648

__device__ float d_feat[NPTS*22];
__device__ float d_qv  [NPTS*24];
__device__ float d_kv  [NPTS*24];
__device__ float d_gv  [NPTS*68];
__device__ float d_part[SPLITS*NPTS*68];
__device__ float d_G   [66*NPTS];
__device__ float d_sh  [NLR*6];
__device__ float d_eb  [2*NLR];
__device__ float d_w3j [W3J_TOTAL];
__device__ float d_coef[2*8*3];

__constant__ int PATH_L[14][3] = {
  {4,0,4},{4,2,4},{6,2,4},{6,0,6},{4,2,6},{6,2,6},
  {4,4,4},{4,6,4},{6,4,4},{6,6,4},{4,4,6},{4,6,6},{6,4,6},{6,6,6}};
__constant__ int PATH_OFF[15] = {
  0,81,486,1071,1240,1825,2670,3399,4452,5505,7026,8079,9600,11121,13318};

// ---------------- W3J (real Wigner/CG) ----------------
struct Cpx { double re, im; };

__device__ __forceinline__ double dev_cg(int j1,int m1,int j2,int m2,int j3,int m3,const double* f){
  if (m1+m2 != m3) return 0.0;
  if (j3 < abs(j1-j2) || j3 > j1+j2) return 0.0;
  double pref = sqrt((2.0*j3+1.0)*f[j3+j1-j2]*f[j3-j1+j2]*f[j1+j2-j3]/f[j1+j2+j3+1]);
  pref *= sqrt(f[j3+m3]*f[j3-m3]*f[j1-m1]*f[j1+m1]*f[j2-m2]*f[j2+m2]);
  double s = 0.0;
  int kmax = j1+j2-j3;
  for (int k=0;k<=kmax;k++){
    int a3=j1-m1-k, a4=j2+m2-k, a5=j3-j2+m1+k, a6=j3-j1-m2+k;
    if (a3<0||a4<0||a5<0||a6<0) continue;
    double t = 1.0/(f[k]*f[kmax-k]*f[a3]*f[a4]*f[a5]*f[a6]);
    s += (k&1)? -t : t;
  }
  return pref*s;
}

__device__ __forceinline__ int unz(int l, int r, int* cols, Cpx* vals){
  const double s2 = 0.70710678118654752440;
  if (r == l){ cols[0]=l; vals[0]=Cpx{1.0,0.0}; return 1; }
  if (r > l){ int m=r-l; double sg=(m&1)?-1.0:1.0;
    cols[0]=l+m; vals[0]=Cpx{sg*s2,0.0};
    cols[1]=l-m; vals[1]=Cpx{s2,0.0}; return 2; }
  int m=l-r; double sg=(m&1)?-1.0:1.0;
  cols[0]=l-m; vals[0]=Cpx{0.0,s2};
  cols[1]=l+m; vals[1]=Cpx{0.0,-sg*s2}; return 2;
}

__device__ __forceinline__ Cpx uent(int l,int r,int c){
  const double s2 = 0.70710678118654752440;
  Cpx z = Cpx{0.0,0.0};
  if (r==l){ if (c==l) z = Cpx{1.0,0.0}; return z; }
  if (r>l){ int m=r-l; double sg=(m&1)?-1.0:1.0;
    if (c==l+m) z = Cpx{sg*s2,0.0}; else if (c==l-m) z = Cpx{s2,0.0}; return z; }
  int m=l-r; double sg=(m&1)?-1.0:1.0;
  if (c==l-m) z = Cpx{0.0,s2}; else if (c==l+m) z = Cpx{0.0,-sg*s2};
  return z;
}

__global__ void k_w3j(){
  int path = blockIdx.x;
  int l1=PATH_L[path][0], l2=PATH_L[path][1], l3=PATH_L[path][2];
  int d1=2*l1+1, d2=2*l2+1, d3=2*l3+1;
  int off=PATH_OFF[path];
  int total=d1*d2*d3;
  __shared__ double Cc[169];
  __shared__ double red[256];
  int tid=threadIdx.x;
  double fct[20]; fct[0]=1.0;
  for (int i=1;i<20;i++) fct[i]=fct[i-1]*(double)i;
  for (int e=tid; e<d1*d2; e+=256){
    int a=e/d2, b=e%d2;
    int m1=a-l1, m2=b-l2, m3=m1+m2;
    Cc[e] = (abs(m3)<=l3) ? dev_cg(l1,m1,l2,m2,l3,m3,fct) : 0.0;
  }
  __syncthreads();
  double tv[9]; double ss=0.0; int cnt=0;
  for (int e=tid; e<total; e+=256){
    int i=e/(d2*d3); int j=(e/d3)%d2; int k=e%d3;
    int c1[2], c2[2]; Cpx u1[2], u2[2];
    int n1 = unz(l1,i,c1,u1);
    int n2 = unz(l2,j,c2,u2);
    double re=0.0;
    for (int ii=0;ii<n1;ii++)
      for (int jj=0;jj<n2;jj++){
        int c = c1[ii]-l1 + c2[jj]-l2 + l3;
        if (c<0 || c>2*l3) continue;
        Cpx u3 = uent(l3,k,c);
        if (u3.re==0.0 && u3.im==0.0) continue;
        double cgv = Cc[c1[ii]*d2 + c2[jj]];
        if (cgv==0.0) continue;
        double pr = u1[ii].re*u2[jj].re - u1[ii].im*u2[jj].im;
        double pi = u1[ii].re*u2[jj].im + u1[ii].im*u2[jj].re;
        re += (pr*u3.re + pi*u3.im)*cgv;
      }
    tv[cnt++]=re; ss+=re*re;
  }
  red[tid]=ss; __syncthreads();
  for (int s=128;s>0;s>>=1){ if (tid<s) red[tid]+=red[tid+s]; __syncthreads(); }
  double rnorm = rsqrt(red[0]);
  cnt=0;
  for (int e=tid; e<total; e+=256) d_w3j[off+e] = (float)(tv[cnt++]*rnorm);
}

// ---------------- spherical harmonics + exp(key bias) ----------------
__global__ void k_sh(const float* __restrict__ pbw, const float* __restrict__ pbb){
  int n = blockIdx.x*256 + threadIdx.x;
  if (n>=NLR) return;
  int h=n>>6, w=n&63;
  double y = -1.0 + 2.0*(double)h/63.0;
  double x = -1.0 + 2.0*(double)w/63.0;
  double r = sqrt(x*x+y*y); if (r < 1e-8) r = 1e-8;
  double xn=x/r, yn=y/r;
  const double c0=0.28209479177387814, c2=1.0925484305920792, c20=0.31539156525252005;
  float sh[6];
  sh[0]=(float)c0;
  sh[1]=(float)(c2*xn*yn);
  sh[2]=0.0f;
  sh[3]=(float)(-c20);
  sh[4]=0.0f;
  sh[5]=(float)(0.5*c2*(xn*xn-yn*yn));
  #pragma unroll
  for (int i=0;i<6;i++) d_sh[n*6+i]=sh[i];
  for (int blk=0;blk<2;blk++){
    float b = pbb[blk];
    #pragma unroll
    for (int i=0;i<6;i++) b = fmaf(sh[i], pbw[blk*6+i], b);
    d_eb[blk*NLR+n]=expf(b);
  }
}

// ---------------- coefficient precompute ----------------
__global__ void k_coef(const float* __restrict__ liw4, const float* __restrict__ liw6,
                       const float* __restrict__ tvw,  const float* __restrict__ tow,
                       const float* __restrict__ low4, const float* __restrict__ low6){
  __shared__ float a_s[96];
  int tid = threadIdx.x;
  if (tid < 96){
    int c = tid & 7; int pp = (tid>>3)%6; int blk = tid/48;
    const float* liw = (pp==0||pp==1||pp==4) ? (liw4+blk*8) : (liw6+blk*8);
    float s=0.f;
    for (int u=0;u<8;u++) s = fmaf(liw[u], tvw[((blk*6+pp)*8+u)*8 + c], s);
    a_s[tid]=s;
  }
  __syncthreads();
  if (tid < 16){
    int q = tid&7, blk = tid>>3;
    const float* liw = (q==0||q==1||q==4||q==5)? (liw4+blk*8) : (liw6+blk*8);
    const float* low = (q<4)? (low4+blk*8) : (low6+blk*8);
    float b[8];
    #pragma unroll
    for (int v=0;v<8;v++){
      float s=0.f;
      for (int u=0;u<8;u++){
        float lu = liw[u];
        for (int w=0;w<8;w++)
          s = fmaf(lu*tow[(((blk*8+q)*8+u)*8+v)*8+w], low[w], s);
      }
      b[v]=s;
    }
    int pbase = (q&1)? 3 : 0;
    const float invs = (1.0f/sqrtf(24.0f)) * (1.0f/16.0f) * (1.0f/sqrtf(8.0f));
    for (int pp=0;pp<3;pp++){
      float s=0.f;
      #pragma unroll
      for (int v=0;v<8;v++) s = fmaf(b[v], a_s[(blk*6+pbase+pp)*8 + v], s);
      d_coef[(blk*8+q)*3+pp] = s*invs;
    }
  }
}

// ---------------- feature init ----------------
__global__ void k_featinit(const float* __restrict__ f4, const float* __restrict__ f6){
  int p = blockIdx.x*256 + threadIdx.x;
  if (p>=NPTS) return;
  #pragma unroll
  for (int i=0;i<9;i++)  d_feat[p*22+i]   = f4[p*9+i];
  #pragma unroll
  for (int j=0;j<13;j++) d_feat[p*22+9+j] = f6[p*13+j];
}

// ---------------- per-point prep: q, k, value tensors g ----------------
__global__ void __launch_bounds__(128) k_prepare(const float* __restrict__ ls4,
                                                 const float* __restrict__ ls6, int blk){
  __shared__ float wv[W3J_OUT_OFF];
  int tid = threadIdx.x;
  for (int i=tid;i<W3J_OUT_OFF;i+=128) wv[i]=d_w3j[i];
  __syncthreads();
  int p = blockIdx.x*128 + tid;
  float f[22];
  float s4=0.f, s6=0.f;
  #pragma unroll
  for (int i=0;i<9;i++){ f[i]=d_feat[p*22+i]; s4=fmaf(f[i],f[i],s4); }
  #pragma unroll
  for (int i=9;i<22;i++){ f[i]=d_feat[p*22+i]; s6=fmaf(f[i],f[i],s6); }
  float inv4=1.f/fmaxf(sqrtf(s4),1e-12f);
  float inv6=1.f/fmaxf(sqrtf(s6),1e-12f);
  float e4=expf(ls4[blk]), e6=expf(ls6[blk]);
  #pragma unroll
  for (int i=0;i<9;i++){ float kk=f[i]*inv4; d_kv[p*24+i]=kk; d_qv[p*24+i]=kk*e4; }
  #pragma unroll
  for (int i=9;i<22;i++){ float kk=f[i]*inv6; d_kv[p*24+i]=kk; d_qv[p*24+i]=kk*e6; }
  d_kv[p*24+22]=0.f; d_kv[p*24+23]=0.f; d_qv[p*24+22]=0.f; d_qv[p*24+23]=0.f;
  int n = p & (NLR-1);
  float sh0=d_sh[n*6];
  float sh2[5];
  #pragma unroll
  for (int j=0;j<5;j++) sh2[j]=d_sh[n*6+1+j];
  float* g = d_gv + p*68;
  { float a[9]; 
    #pragma unroll
    for (int k=0;k<9;k++) a[k]=0.f;
    #pragma unroll 1
    for (int i=0;i<9;i++){ float fi=f[i];
      #pragma unroll
      for (int k=0;k<9;k++) a[k]=fmaf(fi,wv[i*9+k],a[k]); }
    #pragma unroll
    for (int k=0;k<9;k++) g[k]=a[k]*sh0; }
  { float a[9];
    #pragma unroll
    for (int k=0;k<9;k++) a[k]=0.f;
    #pragma unroll 1
    for (int i=0;i<9;i++){ float fi=f[i];
      #pragma unroll 1
      for (int j=0;j<5;j++){ float c=fi*sh2[j];
        #pragma unroll
        for (int k=0;k<9;k++) a[k]=fmaf(c,wv[81+(i*5+j)*9+k],a[k]); } }
    #pragma unroll
    for (int k=0;k<9;k++) g[9+k]=a[k]; }
  { float a[9];
    #pragma unroll
    for (int k=0;k<9;k++) a[k]=0.f;
    #pragma unroll 1
    for (int i=0;i<13;i++){ float fi=f[9+i];
      #pragma unroll 1
      for (int j=0;j<5;j++){ float c=fi*sh2[j];
        #pragma unroll
        for (int k=0;k<9;k++) a[k]=fmaf(c,wv[486+(i*5+j)*9+k],a[k]); } }
    #pragma unroll
    for (int k=0;k<9;k++) g[18+k]=a[k]; }
  { float a[13];
    #pragma unroll
    for (int k=0;k<13;k++) a[k]=0.f;
    #pragma unroll 1
    for (int i=0;i<13;i++){ float fi=f[9+i];
      #pragma unroll
      for (int k=0;k<13;k++) a[k]=fmaf(fi,wv[1071+i*13+k],a[k]); }
    #pragma unroll
    for (int k=0;k<13;k++) g[27+k]=a[k]*sh0; }
  { float a[13];
    #pragma unroll
    for (int k=0;k<13;k++) a[k]=0.f;
    #pragma unroll 1
    for (int i=0;i<9;i++){ float fi=f[i];
      #pragma unroll 1
      for (int j=0;j<5;j++){ float c=fi*sh2[j];
        #pragma unroll
        for (int k=0;k<13;k++) a[k]=fmaf(c,wv[1240+(i*5+j)*13+k],a[k]); } }
    #pragma unroll
    for (int k=0;k<13;k++) g[40+k]=a[k]; }
  { float a[13];
    #pragma unroll
    for (int k=0;k<13;k++) a[k]=0.f;
    #pragma unroll 1
    for (int i=0;i<13;i++){ float fi=f[9+i];
      #pragma unroll 1
      for (int j=0;j<5;j++){ float c=fi*sh2[j];
        #pragma unroll
        for (int k=0;k<13;k++) a[k]=fmaf(c,wv[1825+(i*5+j)*13+k],a[k]); } }
    #pragma unroll
    for (int k=0;k<13;k++) g[53+k]=a[k]; }
  g[66]=1.f; g[67]=0.f;
}

// ---------------- fused attention (split-K, no-max sum-exp) ----------------
__global__ void __launch_bounds__(256) k_attn(int blk){
  __shared__ float ks[MT*24];
  __shared__ float gs[MT*68];
  __shared__ float es[MT];
  int tid = threadIdx.x;
  int sub = tid & 3;
  int row_local = tid >> 2;
  int batch = blockIdx.y;
  int split = blockIdx.z;
  int n = blockIdx.x*64 + row_local;
  int p = batch*NLR + n;
  const float2* qp = (const float2*)(d_qv + p*24 + sub*6);
  float2 qa = qp[0], qb = qp[1], qc = qp[2];
  float acc[20];
  #pragma unroll
  for (int i=0;i<20;i++) acc[i]=0.f;
  int m0 = split*(NLR/SPLITS);
  const int ntiles = (NLR/SPLITS)/MT;
  for (int t=0;t<ntiles;t++){
    int mbase = batch*NLR + m0 + t*MT;
    __syncthreads();
    { const float4* src = (const float4*)(d_kv + mbase*24);
      float4* dst = (float4*)ks;
      for (int i=tid;i<MT*24/4;i+=256) dst[i]=src[i];
      const float4* srcg = (const float4*)(d_gv + mbase*68);
      float4* dstg = (float4*)gs;
      for (int i=tid;i<MT*68/4;i+=256) dstg[i]=srcg[i];
      if (tid < MT) es[tid] = d_eb[blk*NLR + m0 + t*MT + tid];
    }
    __syncthreads();
    #pragma unroll 4
    for (int mi=0;mi<MT;mi++){
      const float2* kk = (const float2*)(ks + mi*24 + sub*6);
      float2 ka=kk[0], kb=kk[1], kc=kk[2];
      float d = qa.x*ka.x + qa.y*ka.y;
      d = fmaf(qb.x,kb.x,d); d = fmaf(qb.y,kb.y,d);
      d = fmaf(qc.x,kc.x,d); d = fmaf(qc.y,kc.y,d);
      d += __shfl_xor_sync(0xffffffffu, d, 1);
      d += __shfl_xor_sync(0xffffffffu, d, 2);
      float w = __expf(d) * es[mi];
      const float4* gg = (const float4*)(gs + mi*68 + sub*16);
      #pragma unroll
      for (int j=0;j<5;j++){
        float4 g4 = gg[j];
        acc[4*j]   = fmaf(w, g4.x, acc[4*j]);
        acc[4*j+1] = fmaf(w, g4.y, acc[4*j+1]);
        acc[4*j+2] = fmaf(w, g4.z, acc[4*j+2]);
        acc[4*j+3] = fmaf(w, g4.w, acc[4*j+3]);
      }
    }
  }
  float4* out = (float4*)(d_part + (size_t)(split*NPTS + p)*68 + sub*16);
  int n4 = (sub==3)?5:4;
  for (int j=0;j<n4;j++) out[j] = make_float4(acc[4*j],acc[4*j+1],acc[4*j+2],acc[4*j+3]);
}

// ---------------- split reduce (also transposes G to [c][p]) ----------------
__global__ void k_reduce(){
  int idx = blockIdx.x*256 + threadIdx.x;
  if (idx >= 66*NPTS) return;
  int c = idx / NPTS, p = idx % NPTS;
  float s=0.f, den=0.f;
  #pragma unroll
  for (int sp=0;sp<SPLITS;sp++){
    const float* base = d_part + (size_t)(sp*NPTS + p)*68;
    s += base[c]; den += base[66];
  }
  d_G[c*NPTS + p] = s/den;
}

// ---------------- per-point output tensor products ----------------
template<int D1,int D2,int D3>
__device__ __forceinline__ void qpath(const float* __restrict__ w3, const float* __restrict__ f,
                                      int p, float c0, float c1, float c2,
                                      int g0, int g1, int g2, float* out){
  #pragma unroll 1
  for (int j=0;j<D2;j++){
    float gm = c0*d_G[(g0+j)*NPTS+p] + c1*d_G[(g1+j)*NPTS+p] + c2*d_G[(g2+j)*NPTS+p];
    #pragma unroll
    for (int i=0;i<D1;i++){
      float cf = gm*f[i];
      #pragma unroll
      for (int k=0;k<D3;k++) out[k] = fmaf(cf, w3[(i*D2+j)*D3+k], out[k]);
    }
  }
}

__global__ void __launch_bounds__(128) k_output(int blk){
  __shared__ float w3s[W3J_OUT_SZ];
  int tid = threadIdx.x;
  for (int i=tid;i<W3J_OUT_SZ;i+=128) w3s[i]=d_w3j[W3J_OUT_OFF+i];
  __syncthreads();
  int p = blockIdx.x*128 + tid;
  float f4[9], f6[13];
  #pragma unroll
  for (int i=0;i<9;i++) f4[i]=d_feat[p*22+i];
  #pragma unroll
  for (int i=0;i<13;i++) f6[i]=d_feat[p*22+9+i];
  float d4[9], d6[13];
  #pragma unroll
  for (int k=0;k<9;k++) d4[k]=0.f;
  #pragma unroll
  for (int k=0;k<13;k++) d6[k]=0.f;
  const float* cf = d_coef + blk*24;
  qpath<9,9,9>   (w3s+0,    f4, p, cf[0], cf[1], cf[2],  0, 9,18, d4);
  qpath<9,13,9>  (w3s+729,  f4, p, cf[3], cf[4], cf[5], 27,40,53, d4);
  qpath<13,9,9>  (w3s+1782, f6, p, cf[6], cf[7], cf[8],  0, 9,18, d4);
  qpath<13,13,9> (w3s+2835, f6, p, cf[9], cf[10],cf[11],27,40,53, d4);
  qpath<9,9,13>  (w3s+4356, f4, p, cf[12],cf[13],cf[14], 0, 9,18, d6);
  qpath<9,13,13> (w3s+5409, f4, p, cf[15],cf[16],cf[17],27,40,53, d6);
  qpath<13,9,13> (w3s+6930, f6, p, cf[18],cf[19],cf[20], 0, 9,18, d6);
  qpath<13,13,13>(w3s+8451, f6, p, cf[21],cf[22],cf[23],27,40,53, d6);
  #pragma unroll
  for (int k=0;k<9;k++)  d_feat[p*22+k]   = f4[k]+d4[k];
  #pragma unroll
  for (int k=0;k<13;k++) d_feat[p*22+9+k] = f6[k]+d6[k];
}

// ---------------- upsample ----------------
__global__ void k_upsample(const float* __restrict__ upw, float* __restrict__ out){
  int idx = blockIdx.x*256 + threadIdx.x;
  if (idx >= NBATCH*65536) return;
  int b = idx >> 16;
  int nh = idx & 65535;
  int rw = nh & 3; int t = nh >> 2; int w = t & 63; t >>= 6; int rh = t & 3; int h = t >> 2;
  int p = b*NLR + h*64 + w;
  float u4 = upw[(rh*4+rw)*2 + 0];
  float u6 = upw[(rh*4+rw)*2 + 1];
  float* o4 = out + (size_t)idx*9;
  float* o6 = out + 1179648 + (size_t)idx*13;
  #pragma unroll
  for (int k=0;k<9;k++)  o4[k] = d_feat[p*22+k]*u4;
  #pragma unroll
  for (int k=0;k<13;k++) o6[k] = d_feat[p*22+9+k]*u6;
}

extern "C" void kernel_launch(void* const* d_in, const int* in_sizes, int n_in,
                              void* d_out, int out_size) {
  const float* f4   = (const float*)d_in[0];
  const float* f6   = (const float*)d_in[1];
  const float* ls4  = (const float*)d_in[2];
  const float* ls6  = (const float*)d_in[3];
  const float* pbw  = (const float*)d_in[4];
  const float* pbb  = (const float*)d_in[5];
  const float* liw4 = (const float*)d_in[6];
  const float* liw6 = (const float*)d_in[7];
  const float* tvw  = (const float*)d_in[8];
  const float* tow  = (const float*)d_in[9];
  const float* low4 = (const float*)d_in[10];
  const float* low6 = (const float*)d_in[11];
  const float* upw  = (const float*)d_in[12];
  float* out = (float*)d_out;

  k_w3j<<<14,256>>>();
  k_sh<<<16,256>>>(pbw, pbb);
  k_coef<<<1,128>>>(liw4, liw6, tvw, tow, low4, low6);
  k_featinit<<<32,256>>>(f4, f6);
  for (int blk=0; blk<2; blk++){
    k_prepare<<<64,128>>>(ls4, ls6, blk);
    k_attn<<<dim3(64,2,SPLITS),256>>>(blk);
    k_reduce<<<(66*NPTS+255)/256,256>>>();
    k_output<<<64,128>>>(blk);
  }
  k_upsample<<<512,256>>>(upw, out);
}

// round 5
// speedup vs baseline: 2.4776x; 2.4776x over previous
#include <cuda_runtime.h>
#include <cuda_bf16.h>
#include <math.h>

#define NBATCH 2
#define NLR    4096
#define NPTS   (NBATCH*NLR)
#define SPLITS 8
#define KT     32
#define RT     128

#define W3J_TOTAL   13318
#define W3J_OUT_OFF 2670

__device__ float d_feat0[NPTS*22];
__device__ float d_feat1[NPTS*22];
__device__ float d_qvT[22*NPTS];
__device__ float d_kvT[22*NPTS];
__device__ __align__(16) float d_gv  [NPTS*68];
__device__ __align__(16) float d_part[SPLITS*NPTS*68];
__device__ float d_G   [66*NPTS];
__device__ float d_sh  [NLR*6];
__device__ float d_eb  [2*NLR];
__device__ float d_w3j [W3J_TOTAL];
__device__ float d_coef[2*8*3];

__constant__ int PATH_L[14][3] = {
  {4,0,4},{4,2,4},{6,2,4},{6,0,6},{4,2,6},{6,2,6},
  {4,4,4},{4,6,4},{6,4,4},{6,6,4},{4,4,6},{4,6,6},{6,4,6},{6,6,6}};
__constant__ int PATH_OFF[15] = {
  0,81,486,1071,1240,1825,2670,3399,4452,5505,7026,8079,9600,11121,13318};

// ---------------- W3J (real Wigner/CG) ----------------
struct Cpx { double re, im; };

__device__ __forceinline__ double dev_cg(int j1,int m1,int j2,int m2,int j3,int m3,const double* f){
  if (m1+m2 != m3) return 0.0;
  if (j3 < abs(j1-j2) || j3 > j1+j2) return 0.0;
  double pref = sqrt((2.0*j3+1.0)*f[j3+j1-j2]*f[j3-j1+j2]*f[j1+j2-j3]/f[j1+j2+j3+1]);
  pref *= sqrt(f[j3+m3]*f[j3-m3]*f[j1-m1]*f[j1+m1]*f[j2-m2]*f[j2+m2]);
  double s = 0.0;
  int kmax = j1+j2-j3;
  for (int k=0;k<=kmax;k++){
    int a3=j1-m1-k, a4=j2+m2-k, a5=j3-j2+m1+k, a6=j3-j1-m2+k;
    if (a3<0||a4<0||a5<0||a6<0) continue;
    double t = 1.0/(f[k]*f[kmax-k]*f[a3]*f[a4]*f[a5]*f[a6]);
    s += (k&1)? -t : t;
  }
  return pref*s;
}

__device__ __forceinline__ int unz(int l, int r, int* cols, Cpx* vals){
  const double s2 = 0.70710678118654752440;
  if (r == l){ cols[0]=l; vals[0]=Cpx{1.0,0.0}; return 1; }
  if (r > l){ int m=r-l; double sg=(m&1)?-1.0:1.0;
    cols[0]=l+m; vals[0]=Cpx{sg*s2,0.0};
    cols[1]=l-m; vals[1]=Cpx{s2,0.0}; return 2; }
  int m=l-r; double sg=(m&1)?-1.0:1.0;
  cols[0]=l-m; vals[0]=Cpx{0.0,s2};
  cols[1]=l+m; vals[1]=Cpx{0.0,-sg*s2}; return 2;
}

__device__ __forceinline__ Cpx uent(int l,int r,int c){
  const double s2 = 0.70710678118654752440;
  Cpx z = Cpx{0.0,0.0};
  if (r==l){ if (c==l) z = Cpx{1.0,0.0}; return z; }
  if (r>l){ int m=r-l; double sg=(m&1)?-1.0:1.0;
    if (c==l+m) z = Cpx{sg*s2,0.0}; else if (c==l-m) z = Cpx{s2,0.0}; return z; }
  int m=l-r; double sg=(m&1)?-1.0:1.0;
  if (c==l-m) z = Cpx{0.0,s2}; else if (c==l+m) z = Cpx{0.0,-sg*s2};
  return z;
}

__global__ void k_w3j(){
  int path = blockIdx.x;
  int l1=PATH_L[path][0], l2=PATH_L[path][1], l3=PATH_L[path][2];
  int d1=2*l1+1, d2=2*l2+1, d3=2*l3+1;
  int off=PATH_OFF[path];
  int total=d1*d2*d3;
  __shared__ double Cc[169];
  __shared__ double red[256];
  int tid=threadIdx.x;
  double fct[20]; fct[0]=1.0;
  for (int i=1;i<20;i++) fct[i]=fct[i-1]*(double)i;
  for (int e=tid; e<d1*d2; e+=256){
    int a=e/d2, b=e%d2;
    int m1=a-l1, m2=b-l2, m3=m1+m2;
    Cc[e] = (abs(m3)<=l3) ? dev_cg(l1,m1,l2,m2,l3,m3,fct) : 0.0;
  }
  __syncthreads();
  double tv[9]; double ss=0.0; int cnt=0;
  for (int e=tid; e<total; e+=256){
    int i=e/(d2*d3); int j=(e/d3)%d2; int k=e%d3;
    int c1[2], c2[2]; Cpx u1[2], u2[2];
    int n1 = unz(l1,i,c1,u1);
    int n2 = unz(l2,j,c2,u2);
    double re=0.0;
    for (int ii=0;ii<n1;ii++)
      for (int jj=0;jj<n2;jj++){
        int c = c1[ii]-l1 + c2[jj]-l2 + l3;
        if (c<0 || c>2*l3) continue;
        Cpx u3 = uent(l3,k,c);
        if (u3.re==0.0 && u3.im==0.0) continue;
        double cgv = Cc[c1[ii]*d2 + c2[jj]];
        if (cgv==0.0) continue;
        double pr = u1[ii].re*u2[jj].re - u1[ii].im*u2[jj].im;
        double pi = u1[ii].re*u2[jj].im + u1[ii].im*u2[jj].re;
        re += (pr*u3.re + pi*u3.im)*cgv;
      }
    tv[cnt++]=re; ss+=re*re;
  }
  red[tid]=ss; __syncthreads();
  for (int s=128;s>0;s>>=1){ if (tid<s) red[tid]+=red[tid+s]; __syncthreads(); }
  double rnorm = rsqrt(red[0]);
  cnt=0;
  for (int e=tid; e<total; e+=256) d_w3j[off+e] = (float)(tv[cnt++]*rnorm);
}

// ---------------- spherical harmonics + exp(key bias) ----------------
__global__ void k_sh(const float* __restrict__ pbw, const float* __restrict__ pbb){
  int n = blockIdx.x*256 + threadIdx.x;
  if (n>=NLR) return;
  int h=n>>6, w=n&63;
  double y = -1.0 + 2.0*(double)h/63.0;
  double x = -1.0 + 2.0*(double)w/63.0;
  double r = sqrt(x*x+y*y); if (r < 1e-8) r = 1e-8;
  double xn=x/r, yn=y/r;
  const double c0=0.28209479177387814, c2=1.0925484305920792, c20=0.31539156525252005;
  float sh[6];
  sh[0]=(float)c0;
  sh[1]=(float)(c2*xn*yn);
  sh[2]=0.0f;
  sh[3]=(float)(-c20);
  sh[4]=0.0f;
  sh[5]=(float)(0.5*c2*(xn*xn-yn*yn));
  #pragma unroll
  for (int i=0;i<6;i++) d_sh[n*6+i]=sh[i];
  for (int blk=0;blk<2;blk++){
    float b = pbb[blk];
    #pragma unroll
    for (int i=0;i<6;i++) b = fmaf(sh[i], pbw[blk*6+i], b);
    d_eb[blk*NLR+n]=expf(b);
  }
}

// ---------------- coefficient precompute ----------------
__global__ void k_coef(const float* __restrict__ liw4, const float* __restrict__ liw6,
                       const float* __restrict__ tvw,  const float* __restrict__ tow,
                       const float* __restrict__ low4, const float* __restrict__ low6){
  __shared__ float a_s[96];
  int tid = threadIdx.x;
  if (tid < 96){
    int c = tid & 7; int pp = (tid>>3)%6; int blk = tid/48;
    const float* liw = (pp==0||pp==1||pp==4) ? (liw4+blk*8) : (liw6+blk*8);
    float s=0.f;
    for (int u=0;u<8;u++) s = fmaf(liw[u], tvw[((blk*6+pp)*8+u)*8 + c], s);
    a_s[tid]=s;
  }
  __syncthreads();
  if (tid < 16){
    int q = tid&7, blk = tid>>3;
    const float* liw = (q==0||q==1||q==4||q==5)? (liw4+blk*8) : (liw6+blk*8);
    const float* low = (q<4)? (low4+blk*8) : (low6+blk*8);
    float b[8];
    #pragma unroll
    for (int v=0;v<8;v++){
      float s=0.f;
      for (int u=0;u<8;u++){
        float lu = liw[u];
        for (int w=0;w<8;w++)
          s = fmaf(lu*tow[(((blk*8+q)*8+u)*8+v)*8+w], low[w], s);
      }
      b[v]=s;
    }
    int pbase = (q&1)? 3 : 0;
    const float invs = (1.0f/sqrtf(24.0f)) * (1.0f/16.0f) * (1.0f/sqrtf(8.0f));
    for (int pp=0;pp<3;pp++){
      float s=0.f;
      #pragma unroll
      for (int v=0;v<8;v++) s = fmaf(b[v], a_s[(blk*6+pbase+pp)*8 + v], s);
      d_coef[(blk*8+q)*3+pp] = s*invs;
    }
  }
}

// ---------------- feature init ----------------
__global__ void k_featinit(const float* __restrict__ f4, const float* __restrict__ f6){
  int p = blockIdx.x*256 + threadIdx.x;
  if (p>=NPTS) return;
  #pragma unroll
  for (int i=0;i<9;i++)  d_feat0[p*22+i]   = f4[p*9+i];
  #pragma unroll
  for (int j=0;j<13;j++) d_feat0[p*22+9+j] = f6[p*13+j];
}

// ---------------- per-point prep: qT, kT, value tensors g (eb folded) -----
__global__ void __launch_bounds__(128) k_prepare(const float* __restrict__ ls4,
                                                 const float* __restrict__ ls6,
                                                 int blk, int sel){
  const float* fin = sel ? d_feat1 : d_feat0;
  __shared__ float wv[W3J_OUT_OFF];
  int tid = threadIdx.x;
  for (int i=tid;i<W3J_OUT_OFF;i+=128) wv[i]=d_w3j[i];
  __syncthreads();
  int p = blockIdx.x*128 + tid;
  float f[22];
  float s4=0.f, s6=0.f;
  #pragma unroll
  for (int i=0;i<9;i++){ f[i]=fin[p*22+i]; s4=fmaf(f[i],f[i],s4); }
  #pragma unroll
  for (int i=9;i<22;i++){ f[i]=fin[p*22+i]; s6=fmaf(f[i],f[i],s6); }
  float inv4=1.f/fmaxf(sqrtf(s4),1e-12f);
  float inv6=1.f/fmaxf(sqrtf(s6),1e-12f);
  float e4=expf(ls4[blk]), e6=expf(ls6[blk]);
  #pragma unroll
  for (int i=0;i<9;i++){ float kk=f[i]*inv4; d_kvT[i*NPTS+p]=kk; d_qvT[i*NPTS+p]=kk*e4; }
  #pragma unroll
  for (int i=9;i<22;i++){ float kk=f[i]*inv6; d_kvT[i*NPTS+p]=kk; d_qvT[i*NPTS+p]=kk*e6; }
  int n = p & (NLR-1);
  float ebv = d_eb[blk*NLR+n];
  float sh0=d_sh[n*6];
  float sh2[5];
  #pragma unroll
  for (int j=0;j<5;j++) sh2[j]=d_sh[n*6+1+j];
  float* g = d_gv + p*68;
  { float a[9];
    #pragma unroll
    for (int k=0;k<9;k++) a[k]=0.f;
    #pragma unroll 1
    for (int i=0;i<9;i++){ float fi=f[i];
      #pragma unroll
      for (int k=0;k<9;k++) a[k]=fmaf(fi,wv[i*9+k],a[k]); }
    #pragma unroll
    for (int k=0;k<9;k++) g[k]=a[k]*sh0*ebv; }
  { float a[9];
    #pragma unroll
    for (int k=0;k<9;k++) a[k]=0.f;
    #pragma unroll 1
    for (int i=0;i<9;i++){ float fi=f[i];
      #pragma unroll 1
      for (int j=0;j<5;j++){ float c=fi*sh2[j];
        #pragma unroll
        for (int k=0;k<9;k++) a[k]=fmaf(c,wv[81+(i*5+j)*9+k],a[k]); } }
    #pragma unroll
    for (int k=0;k<9;k++) g[9+k]=a[k]*ebv; }
  { float a[9];
    #pragma unroll
    for (int k=0;k<9;k++) a[k]=0.f;
    #pragma unroll 1
    for (int i=0;i<13;i++){ float fi=f[9+i];
      #pragma unroll 1
      for (int j=0;j<5;j++){ float c=fi*sh2[j];
        #pragma unroll
        for (int k=0;k<9;k++) a[k]=fmaf(c,wv[486+(i*5+j)*9+k],a[k]); } }
    #pragma unroll
    for (int k=0;k<9;k++) g[18+k]=a[k]*ebv; }
  { float a[13];
    #pragma unroll
    for (int k=0;k<13;k++) a[k]=0.f;
    #pragma unroll 1
    for (int i=0;i<13;i++){ float fi=f[9+i];
      #pragma unroll
      for (int k=0;k<13;k++) a[k]=fmaf(fi,wv[1071+i*13+k],a[k]); }
    #pragma unroll
    for (int k=0;k<13;k++) g[27+k]=a[k]*sh0*ebv; }
  { float a[13];
    #pragma unroll
    for (int k=0;k<13;k++) a[k]=0.f;
    #pragma unroll 1
    for (int i=0;i<9;i++){ float fi=f[i];
      #pragma unroll 1
      for (int j=0;j<5;j++){ float c=fi*sh2[j];
        #pragma unroll
        for (int k=0;k<13;k++) a[k]=fmaf(c,wv[1240+(i*5+j)*13+k],a[k]); } }
    #pragma unroll
    for (int k=0;k<13;k++) g[40+k]=a[k]*ebv; }
  { float a[13];
    #pragma unroll
    for (int k=0;k<13;k++) a[k]=0.f;
    #pragma unroll 1
    for (int i=0;i<13;i++){ float fi=f[9+i];
      #pragma unroll 1
      for (int j=0;j<5;j++){ float c=fi*sh2[j];
        #pragma unroll
        for (int k=0;k<13;k++) a[k]=fmaf(c,wv[1825+(i*5+j)*13+k],a[k]); } }
    #pragma unroll
    for (int k=0;k<13;k++) g[53+k]=a[k]*ebv; }
  g[66]=ebv; g[67]=0.f;
}

// ---------------- tiled attention (static smem, KT=32) ----------------
// CTA: 128 rows x 512 keys (split), key tiles of 32.
// Phase A: S = Q K^T (K=22), thread tile 4 rows x 4 keys -> exp -> Ws[key][row]
// Phase B: acc += W^T G, thread tile 8 rows x 4 cols
__global__ void __launch_bounds__(288,2) k_attn(){
  __shared__ float Qs[22*RT];   // 2816 f
  __shared__ float Ks[22*KT];   // 704 f
  __shared__ float Gs[KT*68];   // 2176 f
  __shared__ float Ws[KT*RT];   // 4096 f
  const int tid = threadIdx.x;
  const int batch = blockIdx.y, split = blockIdx.z;
  const int prow = batch*NLR + blockIdx.x*RT;

  for (int i=tid;i<22*RT;i+=288) Qs[i] = d_qvT[(i>>7)*NPTS + prow + (i&127)];

  const int rgA = tid & 31, kgA = tid >> 5;   // phase A: 4 rows x 4 keys
  const int rgB = tid & 15, cgB = tid >> 4;   // phase B: 8 rows x 4 cols
  float acc[32];
  #pragma unroll
  for (int i=0;i<32;i++) acc[i]=0.f;

  const int m0 = split*(NLR/SPLITS);
  for (int t=0;t<(NLR/SPLITS)/KT;t++){
    const int mbase = batch*NLR + m0 + t*KT;
    __syncthreads();
    for (int i=tid;i<22*KT;i+=288) Ks[i] = d_kvT[(i>>5)*NPTS + mbase + (i&31)];
    { const float4* src = (const float4*)(d_gv) + (size_t)mbase*17;
      float4* dst = (float4*)Gs;
      for (int i=tid;i<KT*17;i+=288) dst[i]=src[i]; }
    __syncthreads();
    if (tid < 256){
      float s[16];
      #pragma unroll
      for (int i=0;i<16;i++) s[i]=0.f;
      #pragma unroll 2
      for (int kk=0;kk<22;kk++){
        float4 q4 = *(const float4*)(Qs + kk*RT + rgA*4);
        float4 k4 = *(const float4*)(Ks + kk*KT + kgA*4);
        #pragma unroll
        for (int r=0;r<4;r++){
          float qv = (r==0)?q4.x:(r==1)?q4.y:(r==2)?q4.z:q4.w;
          s[0*4+r]=fmaf(qv,k4.x,s[0*4+r]);
          s[1*4+r]=fmaf(qv,k4.y,s[1*4+r]);
          s[2*4+r]=fmaf(qv,k4.z,s[2*4+r]);
          s[3*4+r]=fmaf(qv,k4.w,s[3*4+r]);
        }
      }
      #pragma unroll
      for (int j=0;j<4;j++){
        float4 w;
        w.x = __expf(s[j*4+0]);
        w.y = __expf(s[j*4+1]);
        w.z = __expf(s[j*4+2]);
        w.w = __expf(s[j*4+3]);
        *(float4*)(Ws + (kgA*4+j)*RT + rgA*4) = w;
      }
    }
    __syncthreads();
    if (cgB < 17){
      #pragma unroll 2
      for (int key=0;key<KT;key++){
        float4 wa = *(const float4*)(Ws + key*RT + rgB*8);
        float4 wb = *(const float4*)(Ws + key*RT + rgB*8 + 4);
        float4 g4 = *(const float4*)(Gs + key*68 + cgB*4);
        #pragma unroll
        for (int r=0;r<8;r++){
          float wv = (r==0)?wa.x:(r==1)?wa.y:(r==2)?wa.z:(r==3)?wa.w:
                     (r==4)?wb.x:(r==5)?wb.y:(r==6)?wb.z:wb.w;
          acc[r*4+0]=fmaf(wv,g4.x,acc[r*4+0]);
          acc[r*4+1]=fmaf(wv,g4.y,acc[r*4+1]);
          acc[r*4+2]=fmaf(wv,g4.z,acc[r*4+2]);
          acc[r*4+3]=fmaf(wv,g4.w,acc[r*4+3]);
        }
      }
    }
  }
  if (cgB < 17){
    #pragma unroll
    for (int r=0;r<8;r++){
      int p = prow + rgB*8 + r;
      *(float4*)(d_part + ((size_t)split*NPTS + p)*68 + cgB*4) =
        make_float4(acc[r*4],acc[r*4+1],acc[r*4+2],acc[r*4+3]);
    }
  }
}

// ---------------- split reduce + transpose to [c][p] ----------------
__global__ void k_reduce(){
  int p = blockIdx.x*128 + threadIdx.x;
  if (p>=NPTS) return;
  float accv[68];
  #pragma unroll
  for (int i=0;i<68;i++) accv[i]=0.f;
  #pragma unroll
  for (int sp=0;sp<SPLITS;sp++){
    const float4* b = (const float4*)(d_part + ((size_t)sp*NPTS+p)*68);
    #pragma unroll
    for (int i=0;i<17;i++){
      float4 v=b[i];
      accv[i*4+0]+=v.x; accv[i*4+1]+=v.y; accv[i*4+2]+=v.z; accv[i*4+3]+=v.w;
    }
  }
  float inv = 1.f/accv[66];
  #pragma unroll 1
  for (int c=0;c<66;c++) d_G[c*NPTS+p] = accv[c]*inv;
}

// ---------------- per-point output tensor products ----------------
template<int D1,int D2,int D3>
__device__ __forceinline__ void qpath(const float* __restrict__ w3, const float* __restrict__ f,
                                      int p, float c0, float c1, float c2,
                                      int g0, int g1, int g2, float* out){
  #pragma unroll 1
  for (int j=0;j<D2;j++){
    float gm = c0*d_G[(g0+j)*NPTS+p] + c1*d_G[(g1+j)*NPTS+p] + c2*d_G[(g2+j)*NPTS+p];
    #pragma unroll
    for (int i=0;i<D1;i++){
      float cf = gm*f[i];
      #pragma unroll
      for (int k=0;k<D3;k++) out[k] = fmaf(cf, w3[(i*D2+j)*D3+k], out[k]);
    }
  }
}

__global__ void __launch_bounds__(128) k_output(int blk, int sel){
  const float* fin = sel ? d_feat1 : d_feat0;
  float* fout = sel ? d_feat0 : d_feat1;
  __shared__ float w3s[6292];
  int tid = threadIdx.x;
  int half = blockIdx.y;
  int base = half ? 7026 : 2670;
  int len  = half ? 6292 : 4356;
  for (int i=tid;i<len;i+=128) w3s[i]=d_w3j[base+i];
  __syncthreads();
  int p = blockIdx.x*128 + tid;
  float f4[9], f6[13];
  #pragma unroll
  for (int i=0;i<9;i++) f4[i]=fin[p*22+i];
  #pragma unroll
  for (int i=0;i<13;i++) f6[i]=fin[p*22+9+i];
  const float* cf = d_coef + blk*24;
  if (half==0){
    float d4[9];
    #pragma unroll
    for (int k=0;k<9;k++) d4[k]=0.f;
    qpath<9,9,9>   (w3s+0,    f4, p, cf[0], cf[1], cf[2],  0, 9,18, d4);
    qpath<9,13,9>  (w3s+729,  f4, p, cf[3], cf[4], cf[5], 27,40,53, d4);
    qpath<13,9,9>  (w3s+1782, f6, p, cf[6], cf[7], cf[8],  0, 9,18, d4);
    qpath<13,13,9> (w3s+2835, f6, p, cf[9], cf[10],cf[11],27,40,53, d4);
    #pragma unroll
    for (int k=0;k<9;k++) fout[p*22+k] = f4[k]+d4[k];
  } else {
    float d6[13];
    #pragma unroll
    for (int k=0;k<13;k++) d6[k]=0.f;
    qpath<9,9,13>  (w3s+0,    f4, p, cf[12],cf[13],cf[14], 0, 9,18, d6);
    qpath<9,13,13> (w3s+1053, f4, p, cf[15],cf[16],cf[17],27,40,53, d6);
    qpath<13,9,13> (w3s+2574, f6, p, cf[18],cf[19],cf[20], 0, 9,18, d6);
    qpath<13,13,13>(w3s+4095, f6, p, cf[21],cf[22],cf[23],27,40,53, d6);
    #pragma unroll
    for (int k=0;k<13;k++) fout[p*22+9+k] = f6[k]+d6[k];
  }
}

// ---------------- upsample ----------------
__global__ void k_upsample(const float* __restrict__ upw, float* __restrict__ out){
  int idx = blockIdx.x*256 + threadIdx.x;
  if (idx >= NBATCH*65536) return;
  int b = idx >> 16;
  int nh = idx & 65535;
  int rw = nh & 3; int t = nh >> 2; int w = t & 63; t >>= 6; int rh = t & 3; int h = t >> 2;
  int p = b*NLR + h*64 + w;
  float u4 = upw[(rh*4+rw)*2 + 0];
  float u6 = upw[(rh*4+rw)*2 + 1];
  float* o4 = out + (size_t)idx*9;
  float* o6 = out + 1179648 + (size_t)idx*13;
  #pragma unroll
  for (int k=0;k<9;k++)  o4[k] = d_feat0[p*22+k]*u4;
  #pragma unroll
  for (int k=0;k<13;k++) o6[k] = d_feat0[p*22+9+k]*u6;
}

extern "C" void kernel_launch(void* const* d_in, const int* in_sizes, int n_in,
                              void* d_out, int out_size) {
  const float* f4   = (const float*)d_in[0];
  const float* f6   = (const float*)d_in[1];
  const float* ls4  = (const float*)d_in[2];
  const float* ls6  = (const float*)d_in[3];
  const float* pbw  = (const float*)d_in[4];
  const float* pbb  = (const float*)d_in[5];
  const float* liw4 = (const float*)d_in[6];
  const float* liw6 = (const float*)d_in[7];
  const float* tvw  = (const float*)d_in[8];
  const float* tow  = (const float*)d_in[9];
  const float* low4 = (const float*)d_in[10];
  const float* low6 = (const float*)d_in[11];
  const float* upw  = (const float*)d_in[12];
  float* out = (float*)d_out;

  k_w3j<<<14,256>>>();
  k_sh<<<16,256>>>(pbw, pbb);
  k_coef<<<1,128>>>(liw4, liw6, tvw, tow, low4, low6);
  k_featinit<<<32,256>>>(f4, f6);
  for (int blk=0; blk<2; blk++){
    k_prepare<<<64,128>>>(ls4, ls6, blk, blk&1);
    k_attn<<<dim3(NLR/RT, NBATCH, SPLITS), 288>>>();
    k_reduce<<<NPTS/128,128>>>();
    k_output<<<dim3(64,2),128>>>(blk, blk&1);
  }
  k_upsample<<<512,256>>>(upw, out);
}